// round 1
// baseline (speedup 1.0000x reference)
#include <cuda_runtime.h>
#include <math_constants.h>
#include <stdint.h>

#define BATCH 2
#define SEQ   2048
#define NXD   1024
#define NH    16
#define HD    64

// ---- scratch (static device globals; no runtime allocation) ----
__device__ float g_q[(size_t)BATCH*NH*SEQ*HD];
__device__ float g_k[(size_t)BATCH*NH*SEQ*HD];
__device__ float g_v[(size_t)BATCH*NH*SEQ*HD];
__device__ float g_vsuf[(size_t)BATCH*NH*SEQ*HD];
__device__ float g_a[(size_t)BATCH*SEQ*NXD];

// ============================================================================
// Generic tiled FP32 GEMM: C[M,N] = X[M,1024] * W[1024,N] + bias
// MODE 0: X = param (x), scatter into g_q/g_k/g_v as [B,H,S,D]   (N=3072)
// MODE 1: X = g_a, write out[m*N+n]                               (N=1024)
// BM=BN=64, BK=32, 256 threads, 4x4 micro-tile per thread.
// ============================================================================
template<int N, int MODE>
__global__ __launch_bounds__(256) void gemm_kernel(
    const float* __restrict__ Xin, const float* __restrict__ W,
    const float* __restrict__ bias, float* __restrict__ out)
{
    constexpr int BK = 32;
    __shared__ float As[BK*65];   // As[k][m], LD 65 (scalar broadcast reads)
    __shared__ float Bs[BK*68];   // Bs[k][n], LD 68 (16B-aligned float4 reads)

    const float* X = (MODE == 1) ? g_a : Xin;
    const int bm = blockIdx.y * 64;
    const int bn = blockIdx.x * 64;
    const int t = threadIdx.x;
    const int tx = t & 15, ty = t >> 4;

    float acc[4][4] = {};

    const int ca = t & 31, ra = t >> 5;   // A loader: 8 rows x 32 cols per pass
    const int cb = t & 63, rb = t >> 6;   // B loader: 4 rows x 64 cols per pass

    for (int k0 = 0; k0 < NXD; k0 += BK) {
        #pragma unroll
        for (int p = 0; p < 8; p++)
            As[ca*65 + (ra + p*8)] = X[(size_t)(bm + ra + p*8)*NXD + k0 + ca];
        #pragma unroll
        for (int p = 0; p < 8; p++)
            Bs[(rb + p*4)*68 + cb] = W[(size_t)(k0 + rb + p*4)*N + bn + cb];
        __syncthreads();

        #pragma unroll
        for (int kk = 0; kk < BK; kk++) {
            float a0 = As[kk*65 + ty*4 + 0];
            float a1 = As[kk*65 + ty*4 + 1];
            float a2 = As[kk*65 + ty*4 + 2];
            float a3 = As[kk*65 + ty*4 + 3];
            float4 b4 = *(const float4*)&Bs[kk*68 + tx*4];
            acc[0][0] += a0*b4.x; acc[0][1] += a0*b4.y; acc[0][2] += a0*b4.z; acc[0][3] += a0*b4.w;
            acc[1][0] += a1*b4.x; acc[1][1] += a1*b4.y; acc[1][2] += a1*b4.z; acc[1][3] += a1*b4.w;
            acc[2][0] += a2*b4.x; acc[2][1] += a2*b4.y; acc[2][2] += a2*b4.z; acc[2][3] += a2*b4.w;
            acc[3][0] += a3*b4.x; acc[3][1] += a3*b4.y; acc[3][2] += a3*b4.z; acc[3][3] += a3*b4.w;
        }
        __syncthreads();
    }

    #pragma unroll
    for (int i = 0; i < 4; i++) {
        const int m = bm + ty*4 + i;
        #pragma unroll
        for (int j = 0; j < 4; j++) {
            const int n = bn + tx*4 + j;
            float vv = acc[i][j] + bias[n];
            if (MODE == 0) {
                const int which = n >> 10;          // 0=q 1=k 2=v
                const int hh = (n >> 6) & 15;
                const int dd = n & 63;
                const int bb = m >> 11;             // m / 2048
                const int ss = m & 2047;
                float* dst = (which == 0) ? g_q : ((which == 1) ? g_k : g_v);
                dst[(((size_t)(bb*NH + hh))*SEQ + ss)*HD + dd] = vv;
            } else {
                out[(size_t)m*N + n] = vv;
            }
        }
    }
}

// ============================================================================
// V suffix sums: g_vsuf[bh][s][d] = sum_{k>s} g_v[bh][k][d]
// ============================================================================
__global__ void vsuf_kernel()
{
    const int bh = blockIdx.x;
    const int d = threadIdx.x;
    const float* v = g_v + (size_t)bh*SEQ*HD;
    float* vs = g_vsuf + (size_t)bh*SEQ*HD;
    float acc = 0.f;
    for (int s = SEQ - 1; s >= 0; s--) {
        vs[s*HD + d] = acc;
        acc += v[s*HD + d];
    }
}

// ============================================================================
// Fused flash attention with multiplicative relative bias + analytic zero-tail.
// CTA per (bh, 64-row q tile). 256 threads (16x16), each thread 4x4.
// smem: Qs[64][64], KP[64][68] (Kt then aliased as P), Vs[64][64], relw/m/l.
// Writes g_a[b][q][h*64 + d].
// ============================================================================
__global__ __launch_bounds__(256) void attn_kernel(
    const void* __restrict__ rel_raw, const float* __restrict__ rel_emb)
{
    extern __shared__ float sm[];
    float* Qs   = sm;                  // 64*64
    float* KP   = Qs + 64*64;          // 64*68  (K transposed [d][krow], then P [qrow][kcol])
    float* Vs   = KP + 64*68;          // 64*64  [krow][d]
    float* relw = Vs + 64*64;          // 64
    float* m_sh = relw + 64;           // 64
    float* l_sh = m_sh + 64;           // 64

    const int bh = blockIdx.y;
    const int b = bh >> 4, h = bh & 15;
    const int qb = blockIdx.x;
    const int q0 = qb * 64;
    const int t = threadIdx.x;
    const int tx = t & 15, ty = t >> 4;

    // rel element width detection: int64 data has zero high dwords.
    const unsigned int* r32chk = (const unsigned int*)rel_raw;
    const bool is64 = ((r32chk[1] | r32chk[3] | r32chk[5] | r32chk[7] |
                        r32chk[9] | r32chk[11] | r32chk[13] | r32chk[15]) == 0u);
    const int rstride = is64 ? 2 : 1;  // little-endian: low dword of int64 at 2*i
    const int* reli = (const int*)rel_raw;

    // load Q tile
    const float* qp = g_q + ((size_t)bh*SEQ + q0)*HD;
    #pragma unroll
    for (int p = 0; p < 16; p++) {
        int i = t + p*256; int r = i >> 6, c = i & 63;
        Qs[r*64 + c] = qp[r*HD + c];
    }
    if (t < 64) {
        relw[t] = rel_emb[t*NH + h];
        m_sh[t] = -CUDART_INF_F;
        l_sh[t] = 0.f;
    }
    float acc[4][4] = {};
    __syncthreads();

    for (int j = 0; j <= qb; j++) {
        const int k0 = j * 64;
        const float* kp = g_k + ((size_t)bh*SEQ + k0)*HD;
        const float* vp = g_v + ((size_t)bh*SEQ + k0)*HD;
        #pragma unroll
        for (int p = 0; p < 16; p++) {
            int i = t + p*256; int r = i >> 6, c = i & 63;
            KP[c*68 + r] = kp[r*HD + c];   // transposed: [d][krow]
            Vs[r*64 + c] = vp[r*HD + c];
        }
        __syncthreads();

        // S = Q K^T
        float s[4][4] = {};
        #pragma unroll
        for (int kk = 0; kk < 64; kk++) {
            float4 k4 = *(const float4*)&KP[kk*68 + tx*4];
            float a0 = Qs[(ty*4+0)*64 + kk];
            float a1 = Qs[(ty*4+1)*64 + kk];
            float a2 = Qs[(ty*4+2)*64 + kk];
            float a3 = Qs[(ty*4+3)*64 + kk];
            s[0][0] += a0*k4.x; s[0][1] += a0*k4.y; s[0][2] += a0*k4.z; s[0][3] += a0*k4.w;
            s[1][0] += a1*k4.x; s[1][1] += a1*k4.y; s[1][2] += a1*k4.z; s[1][3] += a1*k4.w;
            s[2][0] += a2*k4.x; s[2][1] += a2*k4.y; s[2][2] += a2*k4.z; s[2][3] += a2*k4.w;
            s[3][0] += a3*k4.x; s[3][1] += a3*k4.y; s[3][2] += a3*k4.z; s[3][3] += a3*k4.w;
        }

        // scale, relative bias gather, causal mask within diag block
        const bool diag = (j == qb);
        #pragma unroll
        for (int i = 0; i < 4; i++) {
            const int qr = q0 + ty*4 + i;
            const size_t rbase = (((size_t)b*SEQ + qr)*SEQ + k0);
            #pragma unroll
            for (int jj = 0; jj < 4; jj++) {
                const int kc = k0 + tx*4 + jj;
                if (diag && kc > qr) {
                    s[i][jj] = -1e30f;
                } else {
                    const int idx = reli[(rbase + tx*4 + jj) * rstride];
                    s[i][jj] = s[i][jj] * 0.125f * relw[idx];
                }
            }
        }
        __syncthreads();   // all warps done reading Kt before it becomes P

        // online softmax update (rows ty*4+i owned by this warp's half)
        #pragma unroll
        for (int i = 0; i < 4; i++) {
            const int row = ty*4 + i;
            float rm = fmaxf(fmaxf(s[i][0], s[i][1]), fmaxf(s[i][2], s[i][3]));
            #pragma unroll
            for (int o = 8; o >= 1; o >>= 1)
                rm = fmaxf(rm, __shfl_xor_sync(0xffffffffu, rm, o));
            const float mo = m_sh[row];
            const float mn = fmaxf(mo, rm);
            const float fac = __expf(mo - mn);
            float p0 = __expf(s[i][0] - mn);
            float p1 = __expf(s[i][1] - mn);
            float p2 = __expf(s[i][2] - mn);
            float p3 = __expf(s[i][3] - mn);
            float4 pv = make_float4(p0, p1, p2, p3);
            *(float4*)&KP[row*68 + tx*4] = pv;
            float rs = p0 + p1 + p2 + p3;
            #pragma unroll
            for (int o = 8; o >= 1; o >>= 1)
                rs += __shfl_xor_sync(0xffffffffu, rs, o);   // also orders m_sh read before write
            #pragma unroll
            for (int jj = 0; jj < 4; jj++) acc[i][jj] *= fac;
            if (tx == 0) { m_sh[row] = mn; l_sh[row] = l_sh[row]*fac + rs; }
        }
        __syncwarp();

        // acc += P V   (P rows for this warp were written by this warp)
        #pragma unroll
        for (int kk = 0; kk < 64; kk++) {
            float4 v4 = *(const float4*)&Vs[kk*64 + tx*4];
            float p0 = KP[(ty*4+0)*68 + kk];
            float p1 = KP[(ty*4+1)*68 + kk];
            float p2 = KP[(ty*4+2)*68 + kk];
            float p3 = KP[(ty*4+3)*68 + kk];
            acc[0][0] += p0*v4.x; acc[0][1] += p0*v4.y; acc[0][2] += p0*v4.z; acc[0][3] += p0*v4.w;
            acc[1][0] += p1*v4.x; acc[1][1] += p1*v4.y; acc[1][2] += p1*v4.z; acc[1][3] += p1*v4.w;
            acc[2][0] += p2*v4.x; acc[2][1] += p2*v4.y; acc[2][2] += p2*v4.z; acc[2][3] += p2*v4.w;
            acc[3][0] += p3*v4.x; acc[3][1] += p3*v4.y; acc[3][2] += p3*v4.z; acc[3][3] += p3*v4.w;
        }
        __syncthreads();   // protect Vs/KP before next block's loads
    }

    // merge the analytic zero-score tail (k > q contributes exp(0) and Vsuf)
    #pragma unroll
    for (int i = 0; i < 4; i++) {
        const int row = ty*4 + i;
        const int qr = q0 + row;
        const float mo = m_sh[row];
        float l = l_sh[row];
        float fac = 1.f, et = 0.f;
        if (qr < SEQ - 1) {
            const float mn = fmaxf(mo, 0.f);
            fac = __expf(mo - mn);
            et  = __expf(-mn);
            l = l*fac + (float)(SEQ - 1 - qr) * et;
        }
        const float inv = 1.f / l;
        const float* vsr = g_vsuf + ((size_t)bh*SEQ + qr)*HD;
        float* ap = g_a + ((size_t)(b*SEQ + qr))*NXD + h*HD;
        #pragma unroll
        for (int jj = 0; jj < 4; jj++) {
            const int dd = tx*4 + jj;
            ap[dd] = (acc[i][jj]*fac + et*vsr[dd]) * inv;
        }
    }
}

// ============================================================================
extern "C" void kernel_launch(void* const* d_in, const int* in_sizes, int n_in,
                              void* d_out, int out_size)
{
    const float* x       = (const float*)d_in[0];
    const float* Wqkv    = (const float*)d_in[1];
    const float* bqkv    = (const float*)d_in[2];
    const float* Wproj   = (const float*)d_in[3];
    const float* bproj   = (const float*)d_in[4];
    const float* rel_emb = (const float*)d_in[5];
    const void*  rel     = (const void*)d_in[6];
    float* out = (float*)d_out;

    const size_t attn_smem = (size_t)(64*64 + 64*68 + 64*64 + 192) * sizeof(float); // 50944 B
    cudaFuncSetAttribute(attn_kernel, cudaFuncAttributeMaxDynamicSharedMemorySize, (int)attn_smem);

    gemm_kernel<3*NXD, 0><<<dim3(3*NXD/64, (BATCH*SEQ)/64), 256>>>(x, Wqkv, bqkv, nullptr);
    vsuf_kernel<<<BATCH*NH, HD>>>();
    attn_kernel<<<dim3(SEQ/64, BATCH*NH), 256, attn_smem>>>(rel, rel_emb);
    gemm_kernel<NXD, 1><<<dim3(NXD/64, (BATCH*SEQ)/64), 256>>>(nullptr, Wproj, bproj, out);
}

// round 2
// speedup vs baseline: 2.1131x; 2.1131x over previous
#include <cuda_runtime.h>
#include <math_constants.h>
#include <stdint.h>

#define BATCH 2
#define SEQ   2048
#define NXD   1024
#define NH    16
#define HD    64

// ---- scratch (static device globals; no runtime allocation) ----
__device__ float g_q[(size_t)BATCH*NH*SEQ*HD];
__device__ float g_k[(size_t)BATCH*NH*SEQ*HD];
__device__ float g_v[(size_t)BATCH*NH*SEQ*HD];
__device__ float g_vsuf[(size_t)BATCH*NH*SEQ*HD];
__device__ float g_a[(size_t)BATCH*SEQ*NXD];

// ---- tf32 helpers ----
__device__ __forceinline__ unsigned f2tf(float x){
    unsigned u; asm("cvt.rna.tf32.f32 %0, %1;" : "=r"(u) : "f"(x)); return u;
}
__device__ __forceinline__ void mma8(float* d, const unsigned* a, const unsigned* b){
    asm volatile("mma.sync.aligned.m16n8k8.row.col.f32.tf32.tf32.f32 "
        "{%0,%1,%2,%3},{%4,%5,%6,%7},{%8,%9},{%0,%1,%2,%3};\n"
        : "+f"(d[0]),"+f"(d[1]),"+f"(d[2]),"+f"(d[3])
        : "r"(a[0]),"r"(a[1]),"r"(a[2]),"r"(a[3]),"r"(b[0]),"r"(b[1]));
}

// ============================================================================
// Tensor-core GEMM: C[M=4096, N] = X[M,1024] * W[1024,N] + bias
// MODE 0: X = x param; scatter to g_q/g_k/g_v [B,H,S,D]. q/k cols single-pass
//         TF32, v cols (n>=2048, whole CTAs) 3-pass split.
// MODE 1: X = g_a -> out, always 3-pass split.
// BM=BN=128, BK=32, 256 threads (8 warps as 2m x 4n), warp tile 64x32.
// ============================================================================
template<int N, int MODE>
__global__ __launch_bounds__(256) void gemm_tc(
    const float* __restrict__ Xin, const float* __restrict__ W,
    const float* __restrict__ bias, float* __restrict__ out)
{
    __shared__ float As[128*36];   // [m][k], stride 36
    __shared__ float Bs[128*36];   // [n][k], stride 36

    const float* X = (MODE == 1) ? g_a : Xin;
    const int bm = blockIdx.y * 128, bn = blockIdx.x * 128;
    const int t = threadIdx.x, warp = t >> 5, lane = t & 31;
    const int wm = warp >> 2, wn = warp & 3;
    const int gid = lane >> 2, tig = lane & 3;
    const bool split = (MODE == 1) || (bn >= 2*NXD);

    float acc[4][4][4];
    #pragma unroll
    for (int a = 0; a < 4; a++)
        #pragma unroll
        for (int bq = 0; bq < 4; bq++)
            #pragma unroll
            for (int c = 0; c < 4; c++) acc[a][bq][c] = 0.f;

    const int ar = t >> 3, ac = (t & 7) * 4;
    const int bnc = t & 127, bk0 = t >> 7;

    for (int k0 = 0; k0 < NXD; k0 += 32) {
        #pragma unroll
        for (int p = 0; p < 4; p++) {
            float4 v = *(const float4*)&X[(size_t)(bm + ar + p*32)*NXD + k0 + ac];
            *(float4*)&As[(ar + p*32)*36 + ac] = v;
        }
        #pragma unroll
        for (int p = 0; p < 16; p++) {
            int k = bk0 + p*2;
            Bs[bnc*36 + k] = W[(size_t)(k0 + k)*N + bn + bnc];
        }
        __syncthreads();

        #pragma unroll
        for (int kk = 0; kk < 4; kk++) {
            unsigned ah[4][4], al[4][4];
            #pragma unroll
            for (int im = 0; im < 4; im++) {
                int r = wm*64 + im*16 + gid;
                int c = kk*8 + tig;
                float x0 = As[r*36 + c],     x1 = As[(r+8)*36 + c];
                float x2 = As[r*36 + c + 4], x3 = As[(r+8)*36 + c + 4];
                ah[im][0] = f2tf(x0); ah[im][1] = f2tf(x1);
                ah[im][2] = f2tf(x2); ah[im][3] = f2tf(x3);
                if (split) {
                    al[im][0] = __float_as_uint(x0 - __uint_as_float(ah[im][0]));
                    al[im][1] = __float_as_uint(x1 - __uint_as_float(ah[im][1]));
                    al[im][2] = __float_as_uint(x2 - __uint_as_float(ah[im][2]));
                    al[im][3] = __float_as_uint(x3 - __uint_as_float(ah[im][3]));
                }
            }
            #pragma unroll
            for (int in_ = 0; in_ < 4; in_++) {
                int n = wn*32 + in_*8 + gid;
                float y0 = Bs[n*36 + kk*8 + tig];
                float y1 = Bs[n*36 + kk*8 + tig + 4];
                unsigned bh_[2] = { f2tf(y0), f2tf(y1) };
                #pragma unroll
                for (int im = 0; im < 4; im++) mma8(acc[im][in_], ah[im], bh_);
                if (split) {
                    unsigned bl_[2] = { __float_as_uint(y0 - __uint_as_float(bh_[0])),
                                        __float_as_uint(y1 - __uint_as_float(bh_[1])) };
                    #pragma unroll
                    for (int im = 0; im < 4; im++) {
                        mma8(acc[im][in_], al[im], bh_);
                        mma8(acc[im][in_], ah[im], bl_);
                    }
                }
            }
        }
        __syncthreads();
    }

    #pragma unroll
    for (int im = 0; im < 4; im++) {
        #pragma unroll
        for (int in_ = 0; in_ < 4; in_++) {
            const int r0 = bm + wm*64 + im*16 + gid;
            const int c0 = bn + wn*32 + in_*8 + 2*tig;
            const float b0 = bias[c0], b1 = bias[c0+1];
            float v00 = acc[im][in_][0] + b0, v01 = acc[im][in_][1] + b1;
            float v10 = acc[im][in_][2] + b0, v11 = acc[im][in_][3] + b1;
            if (MODE == 0) {
                const int which = c0 >> 10;
                const int hh = (c0 >> 6) & 15, dd = c0 & 63;
                const int bb = r0 >> 11, ss = r0 & 2047;
                float* dst = (which == 0) ? g_q : ((which == 1) ? g_k : g_v);
                float* base = dst + (((size_t)(bb*NH + hh))*SEQ)*HD + dd;
                *(float2*)&base[(size_t)ss*HD]     = make_float2(v00, v01);
                *(float2*)&base[(size_t)(ss+8)*HD] = make_float2(v10, v11);
            } else {
                *(float2*)&out[(size_t)r0*N + c0]     = make_float2(v00, v01);
                *(float2*)&out[(size_t)(r0+8)*N + c0] = make_float2(v10, v11);
            }
        }
    }
}

// ============================================================================
// V suffix sums (parallel chunked scan): g_vsuf[bh][s][d] = sum_{k>s} v[bh][k][d]
// ============================================================================
__global__ __launch_bounds__(1024) void vsuf_kernel()
{
    const int bh = blockIdx.x;
    const int d = threadIdx.x & 63, ck = threadIdx.x >> 6;   // 16 chunks x 128 rows
    __shared__ float chs[16*64];
    const float* v = g_v + (size_t)bh*SEQ*HD;
    float* vs = g_vsuf + (size_t)bh*SEQ*HD;
    float acc = 0.f;
    for (int s = 127; s >= 0; s--) {
        int idx = (ck*128 + s)*HD + d;
        vs[idx] = acc;
        acc += v[idx];
    }
    chs[ck*64 + d] = acc;
    __syncthreads();
    float carry = 0.f;
    for (int c = ck + 1; c < 16; c++) carry += chs[c*64 + d];
    if (ck < 15)
        for (int s = 0; s < 128; s++)
            vs[(ck*128 + s)*HD + d] += carry;
}

// ============================================================================
// Tensor-core flash attention + multiplicative rel bias + analytic zero tail.
// CTA: 128 threads (4 warps), 64 q-rows; warp owns 16 q-rows.
// QK^T single-pass TF32; P·V 3-pass split TF32.
// smem: Ks[tok][d] 64x68, Vt[d][tok] 64x68, PQ (Q then per-warp P) 64x68, relw.
// ============================================================================
__global__ __launch_bounds__(128) void attn_tc(
    const void* __restrict__ rel_raw, const float* __restrict__ rel_emb)
{
    extern __shared__ float sm[];
    float* Ks   = sm;                 // 64*68
    float* Vt   = Ks + 64*68;         // 64*68
    float* PQ   = Vt + 64*68;         // 64*68
    float* relw = PQ + 64*68;         // 64

    const int bh = blockIdx.y, b = bh >> 4, h = bh & 15;
    const int qb = blockIdx.x, q0 = qb * 64;
    const int t = threadIdx.x, warp = t >> 5, lane = t & 31;
    const int gid = lane >> 2, tig = lane & 3;

    const unsigned* r32chk = (const unsigned*)rel_raw;
    const bool is64 = ((r32chk[1] | r32chk[3] | r32chk[5] | r32chk[7] |
                        r32chk[9] | r32chk[11] | r32chk[13] | r32chk[15]) == 0u);
    const int* reli = (const int*)rel_raw;

    // stage Q into PQ, build register-resident Q fragments
    const float* qp = g_q + ((size_t)bh*SEQ + q0)*HD;
    #pragma unroll
    for (int p = 0; p < 8; p++) {
        int r = (t >> 4) + p*8, c = (t & 15)*4;
        *(float4*)&PQ[r*68 + c] = *(const float4*)&qp[r*HD + c];
    }
    if (t < 64) relw[t] = rel_emb[t*NH + h];
    __syncthreads();

    const int rlo = warp*16 + gid;
    const int qrlo = q0 + rlo, qrhi = qrlo + 8;

    unsigned qf[8][4];
    #pragma unroll
    for (int kk = 0; kk < 8; kk++) {
        int c = kk*8 + tig;
        qf[kk][0] = __float_as_uint(PQ[rlo*68 + c]);
        qf[kk][1] = __float_as_uint(PQ[(rlo+8)*68 + c]);
        qf[kk][2] = __float_as_uint(PQ[rlo*68 + c + 4]);
        qf[kk][3] = __float_as_uint(PQ[(rlo+8)*68 + c + 4]);
    }

    float O[8][4];
    #pragma unroll
    for (int n = 0; n < 8; n++) { O[n][0]=O[n][1]=O[n][2]=O[n][3]=0.f; }
    float mrow[2] = {-CUDART_INF_F, -CUDART_INF_F};
    float lrow[2] = {0.f, 0.f};

    for (int j = 0; j <= qb; j++) {
        __syncthreads();   // prior readers of Ks/Vt done (and Q frag reads on j=0)
        const float* kp = g_k + ((size_t)bh*SEQ + j*64)*HD;
        const float* vp = g_v + ((size_t)bh*SEQ + j*64)*HD;
        #pragma unroll
        for (int p = 0; p < 8; p++) {
            int r = (t >> 4) + p*8, c = (t & 15)*4;
            *(float4*)&Ks[r*68 + c] = *(const float4*)&kp[r*HD + c];
        }
        {
            const int d = t & 63;
            #pragma unroll
            for (int p = 0; p < 32; p++) {
                int tok = (t >> 6) + p*2;
                Vt[d*68 + tok] = vp[tok*HD + d];
            }
        }
        __syncthreads();

        // S = Q K^T (single-pass tf32)
        float S[8][4];
        #pragma unroll
        for (int n = 0; n < 8; n++) { S[n][0]=S[n][1]=S[n][2]=S[n][3]=0.f; }
        #pragma unroll
        for (int kk = 0; kk < 8; kk++) {
            #pragma unroll
            for (int n = 0; n < 8; n++) {
                unsigned bb[2];
                bb[0] = __float_as_uint(Ks[(n*8+gid)*68 + kk*8 + tig]);
                bb[1] = __float_as_uint(Ks[(n*8+gid)*68 + kk*8 + tig + 4]);
                mma8(S[n], qf[kk], bb);
            }
        }

        // scale * rel gather, causal mask on diag block
        const bool diag = (j == qb);
        #pragma unroll
        for (int n = 0; n < 8; n++) {
            const int kc = j*64 + n*8 + 2*tig;
            const size_t rb0 = ((size_t)b*SEQ + qrlo)*SEQ + kc;
            const size_t rb1 = ((size_t)b*SEQ + qrhi)*SEQ + kc;
            int i00, i01, i10, i11;
            if (is64) {
                int4 u0 = *(const int4*)&reli[rb0*2];
                int4 u1 = *(const int4*)&reli[rb1*2];
                i00 = u0.x; i01 = u0.z; i10 = u1.x; i11 = u1.z;
            } else {
                int2 u0 = *(const int2*)&reli[rb0];
                int2 u1 = *(const int2*)&reli[rb1];
                i00 = u0.x; i01 = u0.y; i10 = u1.x; i11 = u1.y;
            }
            S[n][0] = (diag && kc   > qrlo) ? -1e30f : S[n][0]*0.125f*relw[i00];
            S[n][1] = (diag && kc+1 > qrlo) ? -1e30f : S[n][1]*0.125f*relw[i01];
            S[n][2] = (diag && kc   > qrhi) ? -1e30f : S[n][2]*0.125f*relw[i10];
            S[n][3] = (diag && kc+1 > qrhi) ? -1e30f : S[n][3]*0.125f*relw[i11];
        }

        // online softmax (two rows per thread; quad reductions)
        #pragma unroll
        for (int half = 0; half < 2; half++) {
            float mx = -CUDART_INF_F;
            #pragma unroll
            for (int n = 0; n < 8; n++)
                mx = fmaxf(mx, fmaxf(S[n][half*2], S[n][half*2+1]));
            mx = fmaxf(mx, __shfl_xor_sync(0xffffffffu, mx, 1));
            mx = fmaxf(mx, __shfl_xor_sync(0xffffffffu, mx, 2));
            const float mn = fmaxf(mrow[half], mx);
            const float fac = __expf(mrow[half] - mn);
            float rs = 0.f;
            #pragma unroll
            for (int n = 0; n < 8; n++) {
                float p0 = __expf(S[n][half*2]   - mn);
                float p1 = __expf(S[n][half*2+1] - mn);
                S[n][half*2] = p0; S[n][half*2+1] = p1;
                rs += p0 + p1;
            }
            rs += __shfl_xor_sync(0xffffffffu, rs, 1);
            rs += __shfl_xor_sync(0xffffffffu, rs, 2);
            mrow[half] = mn;
            lrow[half] = lrow[half]*fac + rs;
            #pragma unroll
            for (int n = 0; n < 8; n++) { O[n][half*2] *= fac; O[n][half*2+1] *= fac; }
        }

        // write P (own rows only), then P·V with 3-pass split
        #pragma unroll
        for (int n = 0; n < 8; n++) {
            *(float2*)&PQ[rlo*68     + n*8 + 2*tig] = make_float2(S[n][0], S[n][1]);
            *(float2*)&PQ[(rlo+8)*68 + n*8 + 2*tig] = make_float2(S[n][2], S[n][3]);
        }
        __syncwarp();
        #pragma unroll
        for (int kk = 0; kk < 8; kk++) {
            float p0 = PQ[rlo*68     + kk*8 + tig];
            float p1 = PQ[(rlo+8)*68 + kk*8 + tig];
            float p2 = PQ[rlo*68     + kk*8 + tig + 4];
            float p3 = PQ[(rlo+8)*68 + kk*8 + tig + 4];
            unsigned ph[4] = { f2tf(p0), f2tf(p1), f2tf(p2), f2tf(p3) };
            unsigned pl[4] = { __float_as_uint(p0 - __uint_as_float(ph[0])),
                               __float_as_uint(p1 - __uint_as_float(ph[1])),
                               __float_as_uint(p2 - __uint_as_float(ph[2])),
                               __float_as_uint(p3 - __uint_as_float(ph[3])) };
            #pragma unroll
            for (int n = 0; n < 8; n++) {
                float v0 = Vt[(n*8+gid)*68 + kk*8 + tig];
                float v1 = Vt[(n*8+gid)*68 + kk*8 + tig + 4];
                unsigned vh[2] = { f2tf(v0), f2tf(v1) };
                unsigned vl[2] = { __float_as_uint(v0 - __uint_as_float(vh[0])),
                                   __float_as_uint(v1 - __uint_as_float(vh[1])) };
                mma8(O[n], ph, vh);
                mma8(O[n], pl, vh);
                mma8(O[n], ph, vl);
            }
        }
    }

    // merge analytic zero-score tail and write g_a
    #pragma unroll
    for (int half = 0; half < 2; half++) {
        const int qr = half ? qrhi : qrlo;
        const float mo = mrow[half];
        float l = lrow[half];
        float fac = 1.f, et = 0.f;
        if (qr < SEQ - 1) {
            const float mn = fmaxf(mo, 0.f);
            fac = __expf(mo - mn);
            et  = __expf(-mn);
            l = l*fac + (float)(SEQ - 1 - qr) * et;
        }
        const float inv = 1.f / l;
        const float* vsr = g_vsuf + ((size_t)bh*SEQ + qr)*HD;
        float* ap = g_a + ((size_t)(b*SEQ + qr))*NXD + h*HD;
        #pragma unroll
        for (int n = 0; n < 8; n++) {
            const int dd = n*8 + 2*tig;
            float2 vs2 = *(const float2*)&vsr[dd];
            float o0 = (O[n][half*2]   * fac + et*vs2.x) * inv;
            float o1 = (O[n][half*2+1] * fac + et*vs2.y) * inv;
            *(float2*)&ap[dd] = make_float2(o0, o1);
        }
    }
}

// ============================================================================
extern "C" void kernel_launch(void* const* d_in, const int* in_sizes, int n_in,
                              void* d_out, int out_size)
{
    const float* x       = (const float*)d_in[0];
    const float* Wqkv    = (const float*)d_in[1];
    const float* bqkv    = (const float*)d_in[2];
    const float* Wproj   = (const float*)d_in[3];
    const float* bproj   = (const float*)d_in[4];
    const float* rel_emb = (const float*)d_in[5];
    const void*  rel     = (const void*)d_in[6];
    float* out = (float*)d_out;

    const size_t attn_smem = (size_t)(3*64*68 + 64) * sizeof(float);   // 52480 B
    cudaFuncSetAttribute(attn_tc, cudaFuncAttributeMaxDynamicSharedMemorySize, (int)attn_smem);

    gemm_tc<3*NXD, 0><<<dim3(3*NXD/128, (BATCH*SEQ)/128), 256>>>(x, Wqkv, bqkv, nullptr);
    vsuf_kernel<<<BATCH*NH, 1024>>>();
    attn_tc<<<dim3(SEQ/64, BATCH*NH), 128, attn_smem>>>(rel, rel_emb);
    gemm_tc<NXD, 1><<<dim3(NXD/128, (BATCH*SEQ)/128), 256>>>(nullptr, Wproj, bproj, out);
}

// round 3
// speedup vs baseline: 2.3835x; 1.1279x over previous
#include <cuda_runtime.h>
#include <cuda_bf16.h>
#include <math_constants.h>
#include <stdint.h>

#define BATCH 2
#define SEQ   2048
#define NXD   1024
#define NH    16
#define HD    64

// ---- scratch (static device globals; no runtime allocation) ----
__device__ float g_q[(size_t)BATCH*NH*SEQ*HD];
__device__ float g_k[(size_t)BATCH*NH*SEQ*HD];
__device__ float g_v[(size_t)BATCH*NH*SEQ*HD];
__device__ float g_vsuf[(size_t)BATCH*NH*SEQ*HD];
__device__ float g_a[(size_t)BATCH*SEQ*NXD];

// ---- bf16 pack/split helpers ----
// pk(x0,x1): bf16x2 register, low half = x0, high half = x1
__device__ __forceinline__ unsigned pk(float x0, float x1){
    unsigned r; asm("cvt.rn.bf16x2.f32 %0, %1, %2;" : "=r"(r) : "f"(x1), "f"(x0));
    return r;
}
// split pair into hi bf16x2 and lo (residual) bf16x2
__device__ __forceinline__ void sp2(float x0, float x1, unsigned &h, unsigned &l){
    h = pk(x0, x1);
    float f0 = __uint_as_float(h << 16);
    float f1 = __uint_as_float(h & 0xffff0000u);
    l = pk(x0 - f0, x1 - f1);
}
__device__ __forceinline__ void mma16(float* d, const unsigned* a, const unsigned* b){
    asm volatile("mma.sync.aligned.m16n8k16.row.col.f32.bf16.bf16.f32 "
        "{%0,%1,%2,%3},{%4,%5,%6,%7},{%8,%9},{%0,%1,%2,%3};\n"
        : "+f"(d[0]),"+f"(d[1]),"+f"(d[2]),"+f"(d[3])
        : "r"(a[0]),"r"(a[1]),"r"(a[2]),"r"(a[3]),"r"(b[0]),"r"(b[1]));
}

// ============================================================================
// bf16x3 tensor-core GEMM: C[M=4096, N] = X[M,1024] * W[1024,N] + bias
// MODE 0: scatter to g_q/g_k/g_v [B,H,S,D] (N=3072). MODE 1: g_a -> out.
// BM=BN=128, BK=32, 256 threads (8 warps 2m x 4n), warp tile 64x32.
// smem holds pre-split packed bf16x2 pairs (hi/lo), pair-stride 20.
// ============================================================================
template<int N, int MODE>
__global__ __launch_bounds__(256) void gemm_tc(
    const float* __restrict__ Xin, const float* __restrict__ W,
    const float* __restrict__ bias, float* __restrict__ out)
{
    __shared__ unsigned Ah[128*20], Al[128*20];   // [m][kpair], stride 20
    __shared__ unsigned Bh[128*20], Bl[128*20];   // [n][kpair], stride 20

    const float* X = (MODE == 1) ? g_a : Xin;
    const int bm = blockIdx.y * 128, bn = blockIdx.x * 128;
    const int t = threadIdx.x, warp = t >> 5, lane = t & 31;
    const int wm = warp >> 2, wn = warp & 3;
    const int gid = lane >> 2, tig = lane & 3;

    float acc[4][4][4];
    #pragma unroll
    for (int a = 0; a < 4; a++)
        #pragma unroll
        for (int bq = 0; bq < 4; bq++)
            #pragma unroll
            for (int c = 0; c < 4; c++) acc[a][bq][c] = 0.f;

    const int ar = t >> 3, ac = (t & 7) * 4;        // A loader
    const int bnc = t & 127, bg = t >> 7;           // B loader

    for (int k0 = 0; k0 < NXD; k0 += 32) {
        #pragma unroll
        for (int p = 0; p < 4; p++) {
            const int r = ar + p*32;
            float4 v = *(const float4*)&X[(size_t)(bm + r)*NXD + k0 + ac];
            unsigned h0,l0,h1,l1;
            sp2(v.x, v.y, h0, l0); sp2(v.z, v.w, h1, l1);
            Ah[r*20 + (ac>>1)]     = h0; Al[r*20 + (ac>>1)]     = l0;
            Ah[r*20 + (ac>>1) + 1] = h1; Al[r*20 + (ac>>1) + 1] = l1;
        }
        #pragma unroll
        for (int p = 0; p < 8; p++) {
            const int pi = bg + p*2;                 // k-pair index 0..15
            float w0 = W[(size_t)(k0 + 2*pi    )*N + bn + bnc];
            float w1 = W[(size_t)(k0 + 2*pi + 1)*N + bn + bnc];
            unsigned h, l; sp2(w0, w1, h, l);
            Bh[bnc*20 + pi] = h; Bl[bnc*20 + pi] = l;
        }
        __syncthreads();

        #pragma unroll
        for (int kk = 0; kk < 2; kk++) {
            unsigned ah[4][4], al[4][4];
            #pragma unroll
            for (int im = 0; im < 4; im++) {
                const int r = wm*64 + im*16 + gid;
                const int c = kk*8 + tig;
                ah[im][0] = Ah[r*20 + c];     ah[im][1] = Ah[(r+8)*20 + c];
                ah[im][2] = Ah[r*20 + c + 4]; ah[im][3] = Ah[(r+8)*20 + c + 4];
                al[im][0] = Al[r*20 + c];     al[im][1] = Al[(r+8)*20 + c];
                al[im][2] = Al[r*20 + c + 4]; al[im][3] = Al[(r+8)*20 + c + 4];
            }
            #pragma unroll
            for (int in_ = 0; in_ < 4; in_++) {
                const int n = wn*32 + in_*8 + gid;
                unsigned bh_[2] = { Bh[n*20 + kk*8 + tig], Bh[n*20 + kk*8 + tig + 4] };
                unsigned bl_[2] = { Bl[n*20 + kk*8 + tig], Bl[n*20 + kk*8 + tig + 4] };
                #pragma unroll
                for (int im = 0; im < 4; im++) {
                    mma16(acc[im][in_], ah[im], bh_);
                    mma16(acc[im][in_], al[im], bh_);
                    mma16(acc[im][in_], ah[im], bl_);
                }
            }
        }
        __syncthreads();
    }

    #pragma unroll
    for (int im = 0; im < 4; im++) {
        #pragma unroll
        for (int in_ = 0; in_ < 4; in_++) {
            const int r0 = bm + wm*64 + im*16 + gid;
            const int c0 = bn + wn*32 + in_*8 + 2*tig;
            const float b0 = bias[c0], b1 = bias[c0+1];
            float v00 = acc[im][in_][0] + b0, v01 = acc[im][in_][1] + b1;
            float v10 = acc[im][in_][2] + b0, v11 = acc[im][in_][3] + b1;
            if (MODE == 0) {
                const int which = c0 >> 10;
                const int hh = (c0 >> 6) & 15, dd = c0 & 63;
                const int bb = r0 >> 11, ss = r0 & 2047;
                float* dst = (which == 0) ? g_q : ((which == 1) ? g_k : g_v);
                float* base = dst + (((size_t)(bb*NH + hh))*SEQ)*HD + dd;
                *(float2*)&base[(size_t)ss*HD]     = make_float2(v00, v01);
                *(float2*)&base[(size_t)(ss+8)*HD] = make_float2(v10, v11);
            } else {
                *(float2*)&out[(size_t)r0*N + c0]     = make_float2(v00, v01);
                *(float2*)&out[(size_t)(r0+8)*N + c0] = make_float2(v10, v11);
            }
        }
    }
}

// ============================================================================
// V suffix sums (parallel chunked scan)
// ============================================================================
__global__ __launch_bounds__(1024) void vsuf_kernel()
{
    const int bh = blockIdx.x;
    const int d = threadIdx.x & 63, ck = threadIdx.x >> 6;
    __shared__ float chs[16*64];
    const float* v = g_v + (size_t)bh*SEQ*HD;
    float* vs = g_vsuf + (size_t)bh*SEQ*HD;
    float acc = 0.f;
    for (int s = 127; s >= 0; s--) {
        int idx = (ck*128 + s)*HD + d;
        vs[idx] = acc;
        acc += v[idx];
    }
    chs[ck*64 + d] = acc;
    __syncthreads();
    float carry = 0.f;
    for (int c = ck + 1; c < 16; c++) carry += chs[c*64 + d];
    if (ck < 15)
        for (int s = 0; s < 128; s++)
            vs[(ck*128 + s)*HD + d] += carry;
}

// ============================================================================
// bf16x3 flash attention + multiplicative rel bias + analytic zero tail.
// CTA: 128 threads (4 warps), 64 q rows; warp owns 16 q rows.
// smem: packed bf16x2 pair arrays Qh/Ql, Kh/Kl [tok][dpair], Vh/Vl [d][tokpair],
// pair-stride 36 (conflict-free frag reads). P feeds MMA straight from regs.
// ============================================================================
__device__ __forceinline__ void load_tile_pairs(
    const float* __restrict__ src, unsigned* Hh, unsigned* Hl, int t)
{
    #pragma unroll
    for (int p = 0; p < 8; p++) {
        const int r = (t >> 4) + p*8, c = (t & 15)*4;
        float4 v = *(const float4*)&src[r*HD + c];
        unsigned h0,l0,h1,l1;
        sp2(v.x, v.y, h0, l0); sp2(v.z, v.w, h1, l1);
        Hh[r*36 + (c>>1)]     = h0; Hl[r*36 + (c>>1)]     = l0;
        Hh[r*36 + (c>>1) + 1] = h1; Hl[r*36 + (c>>1) + 1] = l1;
    }
}

__global__ __launch_bounds__(128) void attn_tc(
    const void* __restrict__ rel_raw, const float* __restrict__ rel_emb)
{
    extern __shared__ unsigned smu[];
    unsigned* Qh = smu;                 // 64*36
    unsigned* Ql = Qh + 64*36;
    unsigned* Kh = Ql + 64*36;
    unsigned* Kl = Kh + 64*36;
    unsigned* Vh = Kl + 64*36;          // [d][tokpair]
    unsigned* Vl = Vh + 64*36;
    float* relw  = (float*)(Vl + 64*36);// 64

    const int bh = blockIdx.y, b = bh >> 4, h = bh & 15;
    const int qb = blockIdx.x, q0 = qb * 64;
    const int t = threadIdx.x, warp = t >> 5, lane = t & 31;
    const int gid = lane >> 2, tig = lane & 3;

    const unsigned* r32chk = (const unsigned*)rel_raw;
    const bool is64 = ((r32chk[1] | r32chk[3] | r32chk[5] | r32chk[7] |
                        r32chk[9] | r32chk[11] | r32chk[13] | r32chk[15]) == 0u);
    const int* reli = (const int*)rel_raw;

    load_tile_pairs(g_q + ((size_t)bh*SEQ + q0)*HD, Qh, Ql, t);
    if (t < 64) relw[t] = rel_emb[t*NH + h];

    const int rlo = warp*16 + gid;
    const int qrlo = q0 + rlo, qrhi = qrlo + 8;

    float O[8][4];
    #pragma unroll
    for (int n = 0; n < 8; n++) { O[n][0]=O[n][1]=O[n][2]=O[n][3]=0.f; }
    float mrow[2] = {-CUDART_INF_F, -CUDART_INF_F};
    float lrow[2] = {0.f, 0.f};

    for (int j = 0; j <= qb; j++) {
        const float* kp = g_k + ((size_t)bh*SEQ + j*64)*HD;
        const float* vp = g_v + ((size_t)bh*SEQ + j*64)*HD;
        load_tile_pairs(kp, Kh, Kl, t);
        {   // V transpose-pack: Vh[d][tokpair]
            const int d0 = (t & 15)*4, tp0 = t >> 4;
            #pragma unroll
            for (int p = 0; p < 4; p++) {
                const int tp = tp0 + p*8;
                float4 a4 = *(const float4*)&vp[(2*tp  )*HD + d0];
                float4 b4 = *(const float4*)&vp[(2*tp+1)*HD + d0];
                const float av[4] = {a4.x, a4.y, a4.z, a4.w};
                const float bv[4] = {b4.x, b4.y, b4.z, b4.w};
                #pragma unroll
                for (int i = 0; i < 4; i++) {
                    unsigned hh, ll; sp2(av[i], bv[i], hh, ll);
                    Vh[(d0+i)*36 + tp] = hh; Vl[(d0+i)*36 + tp] = ll;
                }
            }
        }
        __syncthreads();

        // S = Q K^T  (bf16 3-pass)
        float S[8][4];
        #pragma unroll
        for (int n = 0; n < 8; n++) { S[n][0]=S[n][1]=S[n][2]=S[n][3]=0.f; }
        #pragma unroll
        for (int kk = 0; kk < 4; kk++) {
            unsigned qh[4], ql[4];
            const int c = kk*8 + tig;
            qh[0] = Qh[rlo*36 + c];     qh[1] = Qh[(rlo+8)*36 + c];
            qh[2] = Qh[rlo*36 + c + 4]; qh[3] = Qh[(rlo+8)*36 + c + 4];
            ql[0] = Ql[rlo*36 + c];     ql[1] = Ql[(rlo+8)*36 + c];
            ql[2] = Ql[rlo*36 + c + 4]; ql[3] = Ql[(rlo+8)*36 + c + 4];
            #pragma unroll
            for (int n = 0; n < 8; n++) {
                const int tok = n*8 + gid;
                unsigned bh_[2] = { Kh[tok*36 + c], Kh[tok*36 + c + 4] };
                unsigned bl_[2] = { Kl[tok*36 + c], Kl[tok*36 + c + 4] };
                mma16(S[n], qh, bh_);
                mma16(S[n], ql, bh_);
                mma16(S[n], qh, bl_);
            }
        }

        // scale * rel gather, causal mask on diag block
        const bool diag = (j == qb);
        #pragma unroll
        for (int n = 0; n < 8; n++) {
            const int kc = j*64 + n*8 + 2*tig;
            const size_t rb0 = ((size_t)b*SEQ + qrlo)*SEQ + kc;
            const size_t rb1 = ((size_t)b*SEQ + qrhi)*SEQ + kc;
            int i00, i01, i10, i11;
            if (is64) {
                int4 u0 = *(const int4*)&reli[rb0*2];
                int4 u1 = *(const int4*)&reli[rb1*2];
                i00 = u0.x; i01 = u0.z; i10 = u1.x; i11 = u1.z;
            } else {
                int2 u0 = *(const int2*)&reli[rb0];
                int2 u1 = *(const int2*)&reli[rb1];
                i00 = u0.x; i01 = u0.y; i10 = u1.x; i11 = u1.y;
            }
            S[n][0] = (diag && kc   > qrlo) ? -1e30f : S[n][0]*0.125f*relw[i00];
            S[n][1] = (diag && kc+1 > qrlo) ? -1e30f : S[n][1]*0.125f*relw[i01];
            S[n][2] = (diag && kc   > qrhi) ? -1e30f : S[n][2]*0.125f*relw[i10];
            S[n][3] = (diag && kc+1 > qrhi) ? -1e30f : S[n][3]*0.125f*relw[i11];
        }

        // online softmax (two rows per thread; quad reductions)
        #pragma unroll
        for (int half = 0; half < 2; half++) {
            float mx = -CUDART_INF_F;
            #pragma unroll
            for (int n = 0; n < 8; n++)
                mx = fmaxf(mx, fmaxf(S[n][half*2], S[n][half*2+1]));
            mx = fmaxf(mx, __shfl_xor_sync(0xffffffffu, mx, 1));
            mx = fmaxf(mx, __shfl_xor_sync(0xffffffffu, mx, 2));
            const float mn = fmaxf(mrow[half], mx);
            const float fac = __expf(mrow[half] - mn);
            float rs = 0.f;
            #pragma unroll
            for (int n = 0; n < 8; n++) {
                float p0 = __expf(S[n][half*2]   - mn);
                float p1 = __expf(S[n][half*2+1] - mn);
                S[n][half*2] = p0; S[n][half*2+1] = p1;
                rs += p0 + p1;
            }
            rs += __shfl_xor_sync(0xffffffffu, rs, 1);
            rs += __shfl_xor_sync(0xffffffffu, rs, 2);
            mrow[half] = mn;
            lrow[half] = lrow[half]*fac + rs;
            #pragma unroll
            for (int n = 0; n < 8; n++) { O[n][half*2] *= fac; O[n][half*2+1] *= fac; }
        }

        // O += P V: P fragments straight from registers (k16 layout matches S)
        #pragma unroll
        for (int kk = 0; kk < 4; kk++) {
            unsigned ph[4], pl[4];
            sp2(S[2*kk][0],   S[2*kk][1],   ph[0], pl[0]);
            sp2(S[2*kk][2],   S[2*kk][3],   ph[1], pl[1]);
            sp2(S[2*kk+1][0], S[2*kk+1][1], ph[2], pl[2]);
            sp2(S[2*kk+1][2], S[2*kk+1][3], ph[3], pl[3]);
            #pragma unroll
            for (int n = 0; n < 8; n++) {
                const int d = n*8 + gid;
                unsigned vh_[2] = { Vh[d*36 + kk*8 + tig], Vh[d*36 + kk*8 + tig + 4] };
                unsigned vl_[2] = { Vl[d*36 + kk*8 + tig], Vl[d*36 + kk*8 + tig + 4] };
                mma16(O[n], ph, vh_);
                mma16(O[n], pl, vh_);
                mma16(O[n], ph, vl_);
            }
        }
        __syncthreads();   // protect K/V (and first-iter Q) before next loads
    }

    // merge analytic zero-score tail and write g_a
    #pragma unroll
    for (int half = 0; half < 2; half++) {
        const int qr = half ? qrhi : qrlo;
        const float mo = mrow[half];
        float l = lrow[half];
        float fac = 1.f, et = 0.f;
        if (qr < SEQ - 1) {
            const float mn = fmaxf(mo, 0.f);
            fac = __expf(mo - mn);
            et  = __expf(-mn);
            l = l*fac + (float)(SEQ - 1 - qr) * et;
        }
        const float inv = 1.f / l;
        const float* vsr = g_vsuf + ((size_t)bh*SEQ + qr)*HD;
        float* ap = g_a + ((size_t)(b*SEQ + qr))*NXD + h*HD;
        #pragma unroll
        for (int n = 0; n < 8; n++) {
            const int dd = n*8 + 2*tig;
            float2 vs2 = *(const float2*)&vsr[dd];
            float o0 = (O[n][half*2]   * fac + et*vs2.x) * inv;
            float o1 = (O[n][half*2+1] * fac + et*vs2.y) * inv;
            *(float2*)&ap[dd] = make_float2(o0, o1);
        }
    }
}

// ============================================================================
extern "C" void kernel_launch(void* const* d_in, const int* in_sizes, int n_in,
                              void* d_out, int out_size)
{
    const float* x       = (const float*)d_in[0];
    const float* Wqkv    = (const float*)d_in[1];
    const float* bqkv    = (const float*)d_in[2];
    const float* Wproj   = (const float*)d_in[3];
    const float* bproj   = (const float*)d_in[4];
    const float* rel_emb = (const float*)d_in[5];
    const void*  rel     = (const void*)d_in[6];
    float* out = (float*)d_out;

    const size_t attn_smem = (size_t)(6*64*36)*4 + 64*4;   // 55552 B
    cudaFuncSetAttribute(attn_tc, cudaFuncAttributeMaxDynamicSharedMemorySize, (int)attn_smem);

    gemm_tc<3*NXD, 0><<<dim3(3*NXD/128, (BATCH*SEQ)/128), 256>>>(x, Wqkv, bqkv, nullptr);
    vsuf_kernel<<<BATCH*NH, 1024>>>();
    attn_tc<<<dim3(SEQ/64, BATCH*NH), 128, attn_smem>>>(rel, rel_emb);
    gemm_tc<NXD, 1><<<dim3(NXD/128, (BATCH*SEQ)/128), 256>>>(nullptr, Wproj, bproj, out);
}

// round 4
// speedup vs baseline: 2.9087x; 1.2204x over previous
#include <cuda_runtime.h>
#include <cuda_bf16.h>
#include <math_constants.h>
#include <stdint.h>

#define BATCH 2
#define SEQ   2048
#define NXD   1024
#define NH    16
#define HD    64

// ---- scratch (static device globals; no runtime allocation) ----
__device__ float g_q[(size_t)BATCH*NH*SEQ*HD];
__device__ float g_k[(size_t)BATCH*NH*SEQ*HD];
__device__ float g_v[(size_t)BATCH*NH*SEQ*HD];
__device__ float g_vsuf[(size_t)BATCH*NH*SEQ*HD];
__device__ float g_a[(size_t)BATCH*SEQ*NXD];
__device__ unsigned char g_rel8[(size_t)BATCH*SEQ*SEQ];

// ---- bf16 pack/split helpers ----
__device__ __forceinline__ unsigned pk(float x0, float x1){
    unsigned r; asm("cvt.rn.bf16x2.f32 %0, %1, %2;" : "=r"(r) : "f"(x1), "f"(x0));
    return r;
}
__device__ __forceinline__ void sp2(float x0, float x1, unsigned &h, unsigned &l){
    h = pk(x0, x1);
    float f0 = __uint_as_float(h << 16);
    float f1 = __uint_as_float(h & 0xffff0000u);
    l = pk(x0 - f0, x1 - f1);
}
__device__ __forceinline__ void mma16(float* d, const unsigned* a, const unsigned* b){
    asm volatile("mma.sync.aligned.m16n8k16.row.col.f32.bf16.bf16.f32 "
        "{%0,%1,%2,%3},{%4,%5,%6,%7},{%8,%9},{%0,%1,%2,%3};\n"
        : "+f"(d[0]),"+f"(d[1]),"+f"(d[2]),"+f"(d[3])
        : "r"(a[0]),"r"(a[1]),"r"(a[2]),"r"(a[3]),"r"(b[0]),"r"(b[1]));
}

// ============================================================================
// rel pack: int64/int32 [B,S,S] -> uint8 (values < 64). 4 elems/thread.
// ============================================================================
__global__ __launch_bounds__(256) void relpack_kernel(const void* __restrict__ rel_raw)
{
    const unsigned* r32 = (const unsigned*)rel_raw;
    const bool is64 = ((r32[1] | r32[3] | r32[5] | r32[7] |
                        r32[9] | r32[11] | r32[13] | r32[15]) == 0u);
    const size_t i = ((size_t)blockIdx.x*256 + threadIdx.x) * 4;
    uchar4 o;
    if (is64) {
        const int4 a = *(const int4*)(r32 + i*2);
        const int4 c = *(const int4*)(r32 + i*2 + 4);
        o = make_uchar4((unsigned char)a.x, (unsigned char)a.z,
                        (unsigned char)c.x, (unsigned char)c.z);
    } else {
        const int4 a = *(const int4*)(r32 + i);
        o = make_uchar4((unsigned char)a.x, (unsigned char)a.y,
                        (unsigned char)a.z, (unsigned char)a.w);
    }
    *(uchar4*)&g_rel8[i] = o;
}

// ============================================================================
// Pipelined bf16 tensor-core GEMM: C[4096, N] = X[4096,1024] * W[1024,N] + bias
// MODE 0: scatter to g_q/g_k/g_v; q/k column-thirds 2-pass, v third 3-pass.
// MODE 1: g_a -> out, 3-pass.
// BM=BN=128, BK=32, 256 threads, double-buffered smem + register prefetch.
// ============================================================================
template<int N, int MODE>
__global__ __launch_bounds__(256) void gemm_tc(
    const float* __restrict__ Xin, const float* __restrict__ W,
    const float* __restrict__ bias, float* __restrict__ out)
{
    constexpr int AS = 128*20;
    extern __shared__ unsigned gsm[];
    unsigned* AhB = gsm;            // [2][AS]
    unsigned* AlB = AhB + 2*AS;
    unsigned* BhB = AlB + 2*AS;
    unsigned* BlB = BhB + 2*AS;

    const float* X = (MODE == 1) ? g_a : Xin;
    const int bm = blockIdx.y * 128, bn = blockIdx.x * 128;
    const bool SPLIT3 = (MODE == 1) || (bn >= 2*NXD);
    const int t = threadIdx.x, warp = t >> 5, lane = t & 31;
    const int wm = warp >> 2, wn = warp & 3;
    const int gid = lane >> 2, tig = lane & 3;

    float acc[4][4][4];
    #pragma unroll
    for (int a = 0; a < 4; a++)
        #pragma unroll
        for (int bq = 0; bq < 4; bq++)
            #pragma unroll
            for (int c = 0; c < 4; c++) acc[a][bq][c] = 0.f;

    const int ar = t >> 3, ac = (t & 7) * 4;
    const int bnc = t & 127, bg = t >> 7;

    float4 apf[4];
    float bpf0[8], bpf1[8];

    auto ldg = [&](int k0) {
        #pragma unroll
        for (int p = 0; p < 4; p++)
            apf[p] = *(const float4*)&X[(size_t)(bm + ar + p*32)*NXD + k0 + ac];
        #pragma unroll
        for (int p = 0; p < 8; p++) {
            const int pi = bg + p*2;
            bpf0[p] = W[(size_t)(k0 + 2*pi    )*N + bn + bnc];
            bpf1[p] = W[(size_t)(k0 + 2*pi + 1)*N + bn + bnc];
        }
    };
    auto sts = [&](int s) {
        unsigned* Ah = AhB + s*AS; unsigned* Al = AlB + s*AS;
        unsigned* Bh = BhB + s*AS; unsigned* Bl = BlB + s*AS;
        #pragma unroll
        for (int p = 0; p < 4; p++) {
            const int r = ar + p*32;
            unsigned h0,l0,h1,l1;
            sp2(apf[p].x, apf[p].y, h0, l0); sp2(apf[p].z, apf[p].w, h1, l1);
            Ah[r*20 + (ac>>1)]     = h0; Al[r*20 + (ac>>1)]     = l0;
            Ah[r*20 + (ac>>1) + 1] = h1; Al[r*20 + (ac>>1) + 1] = l1;
        }
        #pragma unroll
        for (int p = 0; p < 8; p++) {
            const int pi = bg + p*2;
            unsigned h, l; sp2(bpf0[p], bpf1[p], h, l);
            Bh[bnc*20 + pi] = h;
            if (SPLIT3) Bl[bnc*20 + pi] = l;
        }
    };
    auto compute = [&](int s) {
        unsigned* Ah = AhB + s*AS; unsigned* Al = AlB + s*AS;
        unsigned* Bh = BhB + s*AS; unsigned* Bl = BlB + s*AS;
        #pragma unroll
        for (int kk = 0; kk < 2; kk++) {
            unsigned ah[4][4], al[4][4];
            #pragma unroll
            for (int im = 0; im < 4; im++) {
                const int r = wm*64 + im*16 + gid;
                const int c = kk*8 + tig;
                ah[im][0] = Ah[r*20 + c];     ah[im][1] = Ah[(r+8)*20 + c];
                ah[im][2] = Ah[r*20 + c + 4]; ah[im][3] = Ah[(r+8)*20 + c + 4];
                al[im][0] = Al[r*20 + c];     al[im][1] = Al[(r+8)*20 + c];
                al[im][2] = Al[r*20 + c + 4]; al[im][3] = Al[(r+8)*20 + c + 4];
            }
            #pragma unroll
            for (int in_ = 0; in_ < 4; in_++) {
                const int n = wn*32 + in_*8 + gid;
                unsigned bhf[2] = { Bh[n*20 + kk*8 + tig], Bh[n*20 + kk*8 + tig + 4] };
                #pragma unroll
                for (int im = 0; im < 4; im++) {
                    mma16(acc[im][in_], ah[im], bhf);
                    mma16(acc[im][in_], al[im], bhf);
                }
                if (SPLIT3) {
                    unsigned blf[2] = { Bl[n*20 + kk*8 + tig], Bl[n*20 + kk*8 + tig + 4] };
                    #pragma unroll
                    for (int im = 0; im < 4; im++)
                        mma16(acc[im][in_], ah[im], blf);
                }
            }
        }
    };

    ldg(0); sts(0); __syncthreads();
    #pragma unroll 1
    for (int it = 0; it < 31; it++) {
        ldg((it+1)*32);
        compute(it & 1);
        sts((it+1) & 1);
        __syncthreads();
    }
    compute(1);

    #pragma unroll
    for (int im = 0; im < 4; im++) {
        #pragma unroll
        for (int in_ = 0; in_ < 4; in_++) {
            const int r0 = bm + wm*64 + im*16 + gid;
            const int c0 = bn + wn*32 + in_*8 + 2*tig;
            const float b0 = bias[c0], b1 = bias[c0+1];
            float v00 = acc[im][in_][0] + b0, v01 = acc[im][in_][1] + b1;
            float v10 = acc[im][in_][2] + b0, v11 = acc[im][in_][3] + b1;
            if (MODE == 0) {
                const int which = c0 >> 10;
                const int hh = (c0 >> 6) & 15, dd = c0 & 63;
                const int bb = r0 >> 11, ss = r0 & 2047;
                float* dst = (which == 0) ? g_q : ((which == 1) ? g_k : g_v);
                float* base = dst + (((size_t)(bb*NH + hh))*SEQ)*HD + dd;
                *(float2*)&base[(size_t)ss*HD]     = make_float2(v00, v01);
                *(float2*)&base[(size_t)(ss+8)*HD] = make_float2(v10, v11);
            } else {
                *(float2*)&out[(size_t)r0*N + c0]     = make_float2(v00, v01);
                *(float2*)&out[(size_t)(r0+8)*N + c0] = make_float2(v10, v11);
            }
        }
    }
}

// ============================================================================
// V suffix sums (parallel chunked scan)
// ============================================================================
__global__ __launch_bounds__(1024) void vsuf_kernel()
{
    const int bh = blockIdx.x;
    const int d = threadIdx.x & 63, ck = threadIdx.x >> 6;
    __shared__ float chs[16*64];
    const float* v = g_v + (size_t)bh*SEQ*HD;
    float* vs = g_vsuf + (size_t)bh*SEQ*HD;
    float acc = 0.f;
    for (int s = 127; s >= 0; s--) {
        int idx = (ck*128 + s)*HD + d;
        vs[idx] = acc;
        acc += v[idx];
    }
    chs[ck*64 + d] = acc;
    __syncthreads();
    float carry = 0.f;
    for (int c = ck + 1; c < 16; c++) carry += chs[c*64 + d];
    if (ck < 15)
        for (int s = 0; s < 128; s++)
            vs[(ck*128 + s)*HD + d] += carry;
}

// ============================================================================
// Flash attention: 256 threads, 128 q-rows/CTA, 64-token k-blocks.
// QK^T 2-pass bf16 (K hi-only), PV 3-pass. Warps below diagonal skip the last
// k-block. CTAs launched diagonal-descending. rel via packed uint8.
// ============================================================================
__global__ __launch_bounds__(256, 2) void attn_tc(const float* __restrict__ rel_emb)
{
    extern __shared__ unsigned smu[];
    unsigned* Qh = smu;                  // 128*36
    unsigned* Ql = Qh + 128*36;
    unsigned* Kh = Ql + 128*36;          // 64*36 (hi only)
    unsigned* Vh = Kh + 64*36;           // [d][tokpair]
    unsigned* Vl = Vh + 64*36;
    float* relw  = (float*)(Vl + 64*36); // 64

    const int bh = blockIdx.y, b = bh >> 4, h = bh & 15;
    const int qbb = gridDim.x - 1 - blockIdx.x;    // long diagonals first
    const int q0 = qbb * 128;
    const int t = threadIdx.x, warp = t >> 5, lane = t & 31;
    const int gid = lane >> 2, tig = lane & 3;

    // load Q tile (hi+lo)
    const float* qp = g_q + ((size_t)bh*SEQ + q0)*HD;
    #pragma unroll
    for (int p = 0; p < 8; p++) {
        const int r = (t >> 4) + p*16, c = (t & 15)*4;
        float4 v = *(const float4*)&qp[r*HD + c];
        unsigned h0,l0,h1,l1;
        sp2(v.x, v.y, h0, l0); sp2(v.z, v.w, h1, l1);
        Qh[r*36 + (c>>1)]     = h0; Ql[r*36 + (c>>1)]     = l0;
        Qh[r*36 + (c>>1) + 1] = h1; Ql[r*36 + (c>>1) + 1] = l1;
    }
    if (t < 64) relw[t] = rel_emb[t*NH + h];

    const int rlo = warp*16 + gid;
    const int qrlo = q0 + rlo, qrhi = qrlo + 8;

    float O[8][4];
    #pragma unroll
    for (int n = 0; n < 8; n++) { O[n][0]=O[n][1]=O[n][2]=O[n][3]=0.f; }
    float mrow[2] = {-CUDART_INF_F, -CUDART_INF_F};
    float lrow[2] = {0.f, 0.f};

    const int jmax = 2*qbb + 1;
    for (int j = 0; j <= jmax; j++) {
        const float* kp = g_k + ((size_t)bh*SEQ + j*64)*HD;
        const float* vp = g_v + ((size_t)bh*SEQ + j*64)*HD;
        __syncthreads();   // prior compute done before overwriting K/V (also orders Q stores)
        #pragma unroll
        for (int p = 0; p < 4; p++) {
            const int r = (t >> 4) + p*16, c = (t & 15)*4;
            float4 v = *(const float4*)&kp[r*HD + c];
            Kh[r*36 + (c>>1)]     = pk(v.x, v.y);
            Kh[r*36 + (c>>1) + 1] = pk(v.z, v.w);
        }
        {
            const int d0 = (t & 15)*4, tp0 = t >> 4;
            #pragma unroll
            for (int p = 0; p < 2; p++) {
                const int tp = tp0 + p*16;
                float4 a4 = *(const float4*)&vp[(2*tp  )*HD + d0];
                float4 b4 = *(const float4*)&vp[(2*tp+1)*HD + d0];
                const float av[4] = {a4.x, a4.y, a4.z, a4.w};
                const float bv[4] = {b4.x, b4.y, b4.z, b4.w};
                #pragma unroll
                for (int i = 0; i < 4; i++) {
                    unsigned hh, ll; sp2(av[i], bv[i], hh, ll);
                    Vh[(d0+i)*36 + tp] = hh; Vl[(d0+i)*36 + tp] = ll;
                }
            }
        }
        __syncthreads();

        const bool active = (warp >= 4) || (j <= 2*qbb);
        if (active) {
            // S = Q K^T (2-pass)
            float S[8][4];
            #pragma unroll
            for (int n = 0; n < 8; n++) { S[n][0]=S[n][1]=S[n][2]=S[n][3]=0.f; }
            #pragma unroll
            for (int kk = 0; kk < 4; kk++) {
                unsigned qh[4], ql[4];
                const int c = kk*8 + tig;
                qh[0] = Qh[rlo*36 + c];     qh[1] = Qh[(rlo+8)*36 + c];
                qh[2] = Qh[rlo*36 + c + 4]; qh[3] = Qh[(rlo+8)*36 + c + 4];
                ql[0] = Ql[rlo*36 + c];     ql[1] = Ql[(rlo+8)*36 + c];
                ql[2] = Ql[rlo*36 + c + 4]; ql[3] = Ql[(rlo+8)*36 + c + 4];
                #pragma unroll
                for (int n = 0; n < 8; n++) {
                    const int tok = n*8 + gid;
                    unsigned bhf[2] = { Kh[tok*36 + c], Kh[tok*36 + c + 4] };
                    mma16(S[n], qh, bhf);
                    mma16(S[n], ql, bhf);
                }
            }

            // scale * rel gather, causal mask on this warp's diagonal block
            const bool diag = (j == 2*qbb + (warp >> 2));
            #pragma unroll
            for (int n = 0; n < 8; n++) {
                const int kc = j*64 + n*8 + 2*tig;
                uchar2 u0 = *(const uchar2*)&g_rel8[((size_t)b*SEQ + qrlo)*SEQ + kc];
                uchar2 u1 = *(const uchar2*)&g_rel8[((size_t)b*SEQ + qrhi)*SEQ + kc];
                S[n][0] = (diag && kc   > qrlo) ? -1e30f : S[n][0]*0.125f*relw[u0.x];
                S[n][1] = (diag && kc+1 > qrlo) ? -1e30f : S[n][1]*0.125f*relw[u0.y];
                S[n][2] = (diag && kc   > qrhi) ? -1e30f : S[n][2]*0.125f*relw[u1.x];
                S[n][3] = (diag && kc+1 > qrhi) ? -1e30f : S[n][3]*0.125f*relw[u1.y];
            }

            // online softmax
            #pragma unroll
            for (int half = 0; half < 2; half++) {
                float mx = -CUDART_INF_F;
                #pragma unroll
                for (int n = 0; n < 8; n++)
                    mx = fmaxf(mx, fmaxf(S[n][half*2], S[n][half*2+1]));
                mx = fmaxf(mx, __shfl_xor_sync(0xffffffffu, mx, 1));
                mx = fmaxf(mx, __shfl_xor_sync(0xffffffffu, mx, 2));
                const float mn = fmaxf(mrow[half], mx);
                const float fac = __expf(mrow[half] - mn);
                float rs = 0.f;
                #pragma unroll
                for (int n = 0; n < 8; n++) {
                    float p0 = __expf(S[n][half*2]   - mn);
                    float p1 = __expf(S[n][half*2+1] - mn);
                    S[n][half*2] = p0; S[n][half*2+1] = p1;
                    rs += p0 + p1;
                }
                rs += __shfl_xor_sync(0xffffffffu, rs, 1);
                rs += __shfl_xor_sync(0xffffffffu, rs, 2);
                mrow[half] = mn;
                lrow[half] = lrow[half]*fac + rs;
                #pragma unroll
                for (int n = 0; n < 8; n++) { O[n][half*2] *= fac; O[n][half*2+1] *= fac; }
            }

            // O += P V (3-pass; P straight from registers)
            #pragma unroll
            for (int kk = 0; kk < 4; kk++) {
                unsigned ph[4], pl[4];
                sp2(S[2*kk][0],   S[2*kk][1],   ph[0], pl[0]);
                sp2(S[2*kk][2],   S[2*kk][3],   ph[1], pl[1]);
                sp2(S[2*kk+1][0], S[2*kk+1][1], ph[2], pl[2]);
                sp2(S[2*kk+1][2], S[2*kk+1][3], ph[3], pl[3]);
                #pragma unroll
                for (int n = 0; n < 8; n++) {
                    const int d = n*8 + gid;
                    unsigned vhf[2] = { Vh[d*36 + kk*8 + tig], Vh[d*36 + kk*8 + tig + 4] };
                    unsigned vlf[2] = { Vl[d*36 + kk*8 + tig], Vl[d*36 + kk*8 + tig + 4] };
                    mma16(O[n], ph, vhf);
                    mma16(O[n], pl, vhf);
                    mma16(O[n], ph, vlf);
                }
            }
        }
    }

    // merge analytic zero-score tail and write g_a
    #pragma unroll
    for (int half = 0; half < 2; half++) {
        const int qr = half ? qrhi : qrlo;
        const float mo = mrow[half];
        float l = lrow[half];
        float fac = 1.f, et = 0.f;
        if (qr < SEQ - 1) {
            const float mn = fmaxf(mo, 0.f);
            fac = __expf(mo - mn);
            et  = __expf(-mn);
            l = l*fac + (float)(SEQ - 1 - qr) * et;
        }
        const float inv = 1.f / l;
        const float* vsr = g_vsuf + ((size_t)bh*SEQ + qr)*HD;
        float* ap = g_a + ((size_t)(b*SEQ + qr))*NXD + h*HD;
        #pragma unroll
        for (int n = 0; n < 8; n++) {
            const int dd = n*8 + 2*tig;
            float2 vs2 = *(const float2*)&vsr[dd];
            float o0 = (O[n][half*2]   * fac + et*vs2.x) * inv;
            float o1 = (O[n][half*2+1] * fac + et*vs2.y) * inv;
            *(float2*)&ap[dd] = make_float2(o0, o1);
        }
    }
}

// ============================================================================
extern "C" void kernel_launch(void* const* d_in, const int* in_sizes, int n_in,
                              void* d_out, int out_size)
{
    const float* x       = (const float*)d_in[0];
    const float* Wqkv    = (const float*)d_in[1];
    const float* bqkv    = (const float*)d_in[2];
    const float* Wproj   = (const float*)d_in[3];
    const float* bproj   = (const float*)d_in[4];
    const float* rel_emb = (const float*)d_in[5];
    const void*  rel     = (const void*)d_in[6];
    float* out = (float*)d_out;

    const int gemm_smem = 2*4*128*20*4;                       // 81920 B
    const int attn_smem = (2*128*36 + 3*64*36 + 64) * 4;      // 64768 B
    cudaFuncSetAttribute(gemm_tc<3*NXD,0>, cudaFuncAttributeMaxDynamicSharedMemorySize, gemm_smem);
    cudaFuncSetAttribute(gemm_tc<NXD,1>,   cudaFuncAttributeMaxDynamicSharedMemorySize, gemm_smem);
    cudaFuncSetAttribute(attn_tc, cudaFuncAttributeMaxDynamicSharedMemorySize, attn_smem);

    relpack_kernel<<<(BATCH*SEQ*SEQ/4)/256, 256>>>(rel);
    gemm_tc<3*NXD, 0><<<dim3(3*NXD/128, (BATCH*SEQ)/128), 256, gemm_smem>>>(x, Wqkv, bqkv, nullptr);
    vsuf_kernel<<<BATCH*NH, 1024>>>();
    attn_tc<<<dim3(SEQ/128, BATCH*NH), 256, attn_smem>>>(rel_emb);
    gemm_tc<NXD, 1><<<dim3(NXD/128, (BATCH*SEQ)/128), 256, gemm_smem>>>(nullptr, Wproj, bproj, out);
}